// round 7
// baseline (speedup 1.0000x reference)
#include <cuda_runtime.h>

// DWT Haar L1 loss — single fused persistent kernel, exactly 4 CTAs per SM
// (grid 592 = 148*4), uniform work, batched streaming loads,
// last-block-ticket finalize.
//
// loss = sum_over_2x2_blocks( max(|a+b|,|c+d|) + max(|a-b|,|c-d|) ) / 6291456
// where a,b,c,d are the (pred-target) diffs of the 2x2 block.
// (Haar is linear; |u+v|+|u-v| = 2*max(|u|,|v|) cancels the 0.5 factor.)

#define NBLOCKS     592                      // 148 SMs * 4 CTAs
#define NTHREADS    256
#define STRIDE      (NBLOCKS * NTHREADS)     // 151552 groups per step
#define BASE_ITERS  20                       // all threads
#define EXTRA_THRESH 114688u                 // first 114688 threads do 1 more
                                             // 151552*20 + 114688 = 3145728 ✓
#define INV_COUNT   (1.0 / 6291456.0)

__device__ float    g_partials[NBLOCKS];
__device__ unsigned g_count = 0;

__device__ __forceinline__ unsigned group_base(unsigned i) {
    // i = img*2^15 + r*2^7 + g  -> elem base = img*262144 + 2r*512 + g*4
    return ((i >> 7) << 10) | ((i & 127u) << 2);
}

__device__ __forceinline__ float block_term(
    float4 p0, float4 p1, float4 t0, float4 t1)
{
    float a0 = p0.x - t0.x, b0 = p0.y - t0.y;
    float c0 = p1.x - t1.x, d0 = p1.y - t1.y;
    float a1 = p0.z - t0.z, b1 = p0.w - t0.w;
    float c1 = p1.z - t1.z, d1 = p1.w - t1.w;

    return fmaxf(fabsf(a0 + b0), fabsf(c0 + d0))
         + fmaxf(fabsf(a0 - b0), fabsf(c0 - d0))
         + fmaxf(fabsf(a1 + b1), fabsf(c1 + d1))
         + fmaxf(fabsf(a1 - b1), fabsf(c1 - d1));
}

__device__ __forceinline__ float group1(const float* __restrict__ pred,
                                        const float* __restrict__ tgt,
                                        unsigned i)
{
    unsigned b = group_base(i);
    float4 p0 = __ldcs(reinterpret_cast<const float4*>(pred + b));
    float4 p1 = __ldcs(reinterpret_cast<const float4*>(pred + b + 512));
    float4 t0 = __ldcs(reinterpret_cast<const float4*>(tgt  + b));
    float4 t1 = __ldcs(reinterpret_cast<const float4*>(tgt  + b + 512));
    return block_term(p0, p1, t0, t1);
}

__global__ __launch_bounds__(NTHREADS, 4) void dwt_fused_kernel(
    const float* __restrict__ pred, const float* __restrict__ tgt,
    float* __restrict__ out)
{
    const unsigned i0 = blockIdx.x * NTHREADS + threadIdx.x;

    float acc = 0.0f;
    #pragma unroll 1
    for (int k = 0; k < BASE_ITERS; k += 2) {
        unsigned ba = group_base(i0 + (unsigned)k * STRIDE);
        unsigned bb = group_base(i0 + (unsigned)(k + 1) * STRIDE);

        // 8 independent 128-bit streaming loads, front-batched for MLP
        float4 pa0 = __ldcs(reinterpret_cast<const float4*>(pred + ba));
        float4 pa1 = __ldcs(reinterpret_cast<const float4*>(pred + ba + 512));
        float4 ta0 = __ldcs(reinterpret_cast<const float4*>(tgt  + ba));
        float4 ta1 = __ldcs(reinterpret_cast<const float4*>(tgt  + ba + 512));
        float4 pb0 = __ldcs(reinterpret_cast<const float4*>(pred + bb));
        float4 pb1 = __ldcs(reinterpret_cast<const float4*>(pred + bb + 512));
        float4 tb0 = __ldcs(reinterpret_cast<const float4*>(tgt  + bb));
        float4 tb1 = __ldcs(reinterpret_cast<const float4*>(tgt  + bb + 512));

        acc += block_term(pa0, pa1, ta0, ta1);
        acc += block_term(pb0, pb1, tb0, tb1);
    }

    // tail: first EXTRA_THRESH threads (whole blocks 0..447) do one more group
    if (i0 < EXTRA_THRESH)
        acc += group1(pred, tgt, i0 + (unsigned)BASE_ITERS * STRIDE);

    // ---- intra-block reduction ----
    #pragma unroll
    for (int off = 16; off > 0; off >>= 1)
        acc += __shfl_down_sync(0xFFFFFFFFu, acc, off);

    __shared__ float warp_sums[NTHREADS / 32];
    __shared__ bool  is_last;
    int lane = threadIdx.x & 31;
    int wid  = threadIdx.x >> 5;
    if (lane == 0) warp_sums[wid] = acc;
    __syncthreads();

    if (wid == 0) {
        float v = (lane < NTHREADS / 32) ? warp_sums[lane] : 0.0f;
        #pragma unroll
        for (int off = 4; off > 0; off >>= 1)
            v += __shfl_down_sync(0xFFFFFFFFu, v, off);
        if (lane == 0) {
            g_partials[blockIdx.x] = v;       // overwrite: no init needed
            __threadfence();                  // publish partial before ticket
            unsigned t = atomicAdd(&g_count, 1u);
            is_last = (t == NBLOCKS - 1);
        }
    }
    __syncthreads();

    // ---- last block finalizes ----
    if (is_last) {
        if (threadIdx.x == 0) {
            g_count = 0;                      // reset for next graph replay
            __threadfence();
        }

        double s = 0.0;
        for (int idx = threadIdx.x; idx < NBLOCKS; idx += NTHREADS)
            s += (double)g_partials[idx];

        #pragma unroll
        for (int off = 16; off > 0; off >>= 1)
            s += __shfl_down_sync(0xFFFFFFFFu, s, off);

        __shared__ double dwarp_sums[NTHREADS / 32];
        if (lane == 0) dwarp_sums[wid] = s;
        __syncthreads();

        if (wid == 0) {
            double v = (lane < NTHREADS / 32) ? dwarp_sums[lane] : 0.0;
            #pragma unroll
            for (int off = 4; off > 0; off >>= 1)
                v += __shfl_down_sync(0xFFFFFFFFu, v, off);
            if (lane == 0)
                out[0] = (float)(v * INV_COUNT);
        }
    }
}

extern "C" void kernel_launch(void* const* d_in, const int* in_sizes, int n_in,
                              void* d_out, int out_size) {
    const float* pred = (const float*)d_in[0];
    const float* tgt  = (const float*)d_in[1];
    float* out = (float*)d_out;

    dwt_fused_kernel<<<NBLOCKS, NTHREADS>>>(pred, tgt, out);
}

// round 10
// speedup vs baseline: 1.0009x; 1.0009x over previous
#include <cuda_runtime.h>

// DWT Haar L1 loss — single fused persistent kernel (grid 512 x 256, uniform
// 24 groups/thread, batch-2 streaming loads), block-level double atomicAdd
// epilogue with last-ticket finalize (no partials array, no final reduce tree).
//
// loss = sum_over_2x2_blocks( max(|a+b|,|c+d|) + max(|a-b|,|c-d|) ) / 6291456
// where a,b,c,d are the (pred-target) diffs of the 2x2 block.
// (Haar is linear; |u+v|+|u-v| = 2*max(|u|,|v|) cancels the 0.5 factor.)

#define NBLOCKS     512
#define NTHREADS    256
#define STRIDE      (NBLOCKS * NTHREADS)     // 131072 groups per step
#define ITERS       24                        // 512*256*24 = 3145728 groups ✓
#define INV_COUNT   (1.0 / 6291456.0)

__device__ double   g_sum   = 0.0;
__device__ unsigned g_count = 0;

__device__ __forceinline__ unsigned group_base(unsigned i) {
    // i = img*2^15 + r*2^7 + g  -> elem base = img*262144 + 2r*512 + g*4
    return ((i >> 7) << 10) | ((i & 127u) << 2);
}

__device__ __forceinline__ float block_term(
    float4 p0, float4 p1, float4 t0, float4 t1)
{
    float a0 = p0.x - t0.x, b0 = p0.y - t0.y;
    float c0 = p1.x - t1.x, d0 = p1.y - t1.y;
    float a1 = p0.z - t0.z, b1 = p0.w - t0.w;
    float c1 = p1.z - t1.z, d1 = p1.w - t1.w;

    return fmaxf(fabsf(a0 + b0), fabsf(c0 + d0))
         + fmaxf(fabsf(a0 - b0), fabsf(c0 - d0))
         + fmaxf(fabsf(a1 + b1), fabsf(c1 + d1))
         + fmaxf(fabsf(a1 - b1), fabsf(c1 - d1));
}

__global__ __launch_bounds__(NTHREADS, 4) void dwt_fused_kernel(
    const float* __restrict__ pred, const float* __restrict__ tgt,
    float* __restrict__ out)
{
    const unsigned i0 = blockIdx.x * NTHREADS + threadIdx.x;

    float acc = 0.0f;
    #pragma unroll 1
    for (int k = 0; k < ITERS; k += 2) {
        unsigned ba = group_base(i0 + (unsigned)k * STRIDE);
        unsigned bb = group_base(i0 + (unsigned)(k + 1) * STRIDE);

        // 8 independent 128-bit streaming loads, front-batched for MLP
        float4 pa0 = __ldcs(reinterpret_cast<const float4*>(pred + ba));
        float4 pa1 = __ldcs(reinterpret_cast<const float4*>(pred + ba + 512));
        float4 ta0 = __ldcs(reinterpret_cast<const float4*>(tgt  + ba));
        float4 ta1 = __ldcs(reinterpret_cast<const float4*>(tgt  + ba + 512));
        float4 pb0 = __ldcs(reinterpret_cast<const float4*>(pred + bb));
        float4 pb1 = __ldcs(reinterpret_cast<const float4*>(pred + bb + 512));
        float4 tb0 = __ldcs(reinterpret_cast<const float4*>(tgt  + bb));
        float4 tb1 = __ldcs(reinterpret_cast<const float4*>(tgt  + bb + 512));

        acc += block_term(pa0, pa1, ta0, ta1);
        acc += block_term(pb0, pb1, tb0, tb1);
    }

    // ---- intra-block reduction ----
    #pragma unroll
    for (int off = 16; off > 0; off >>= 1)
        acc += __shfl_down_sync(0xFFFFFFFFu, acc, off);

    __shared__ float warp_sums[NTHREADS / 32];
    int lane = threadIdx.x & 31;
    int wid  = threadIdx.x >> 5;
    if (lane == 0) warp_sums[wid] = acc;
    __syncthreads();

    if (wid == 0) {
        float v = (lane < NTHREADS / 32) ? warp_sums[lane] : 0.0f;
        #pragma unroll
        for (int off = 4; off > 0; off >>= 1)
            v += __shfl_down_sync(0xFFFFFFFFu, v, off);
        if (lane == 0) {
            atomicAdd(&g_sum, (double)v);     // accumulate in double
            __threadfence();                  // publish before ticket
            unsigned t = atomicAdd(&g_count, 1u);
            if (t == NBLOCKS - 1) {
                // last block: all g_sum adds are visible (each preceded its ticket)
                out[0] = (float)(g_sum * INV_COUNT);
                g_sum   = 0.0;                // reset for next graph replay
                g_count = 0;
                __threadfence();
            }
        }
    }
}

extern "C" void kernel_launch(void* const* d_in, const int* in_sizes, int n_in,
                              void* d_out, int out_size) {
    const float* pred = (const float*)d_in[0];
    const float* tgt  = (const float*)d_in[1];
    float* out = (float*)d_out;

    dwt_fused_kernel<<<NBLOCKS, NTHREADS>>>(pred, tgt, out);
}

// round 13
// speedup vs baseline: 1.0100x; 1.0091x over previous
#include <cuda_runtime.h>

// DWT Haar L1 loss — single fused persistent kernel (grid 512 x 256, uniform
// 24 groups/thread, batch-3 streaming loads = 12 front-batched LDG.128/iter),
// double-atomic epilogue with last-ticket finalize.
//
// loss = sum_over_2x2_blocks( max(|a+b|,|c+d|) + max(|a-b|,|c-d|) ) / 6291456
// where a,b,c,d are the (pred-target) diffs of the 2x2 block.
// (Haar is linear; |u+v|+|u-v| = 2*max(|u|,|v|) cancels the 0.5 factor.)

#define NBLOCKS     512
#define NTHREADS    256
#define STRIDE      (NBLOCKS * NTHREADS)     // 131072 groups per step
#define ITERS       24                        // 512*256*24 = 3145728 groups ✓
#define INV_COUNT   (1.0 / 6291456.0)

__device__ double   g_sum   = 0.0;
__device__ unsigned g_count = 0;

__device__ __forceinline__ unsigned group_base(unsigned i) {
    // i = img*2^15 + r*2^7 + g  -> elem base = img*262144 + 2r*512 + g*4
    return ((i >> 7) << 10) | ((i & 127u) << 2);
}

__device__ __forceinline__ float block_term(
    float4 p0, float4 p1, float4 t0, float4 t1)
{
    float a0 = p0.x - t0.x, b0 = p0.y - t0.y;
    float c0 = p1.x - t1.x, d0 = p1.y - t1.y;
    float a1 = p0.z - t0.z, b1 = p0.w - t0.w;
    float c1 = p1.z - t1.z, d1 = p1.w - t1.w;

    return fmaxf(fabsf(a0 + b0), fabsf(c0 + d0))
         + fmaxf(fabsf(a0 - b0), fabsf(c0 - d0))
         + fmaxf(fabsf(a1 + b1), fabsf(c1 + d1))
         + fmaxf(fabsf(a1 - b1), fabsf(c1 - d1));
}

__global__ __launch_bounds__(NTHREADS, 4) void dwt_fused_kernel(
    const float* __restrict__ pred, const float* __restrict__ tgt,
    float* __restrict__ out)
{
    const unsigned i0 = blockIdx.x * NTHREADS + threadIdx.x;

    float acc = 0.0f;
    #pragma unroll 1
    for (int k = 0; k < ITERS; k += 3) {
        unsigned ba = group_base(i0 + (unsigned)k * STRIDE);
        unsigned bb = group_base(i0 + (unsigned)(k + 1) * STRIDE);
        unsigned bc = group_base(i0 + (unsigned)(k + 2) * STRIDE);

        // 12 independent 128-bit streaming loads, front-batched for MLP
        float4 pa0 = __ldcs(reinterpret_cast<const float4*>(pred + ba));
        float4 pa1 = __ldcs(reinterpret_cast<const float4*>(pred + ba + 512));
        float4 ta0 = __ldcs(reinterpret_cast<const float4*>(tgt  + ba));
        float4 ta1 = __ldcs(reinterpret_cast<const float4*>(tgt  + ba + 512));
        float4 pb0 = __ldcs(reinterpret_cast<const float4*>(pred + bb));
        float4 pb1 = __ldcs(reinterpret_cast<const float4*>(pred + bb + 512));
        float4 tb0 = __ldcs(reinterpret_cast<const float4*>(tgt  + bb));
        float4 tb1 = __ldcs(reinterpret_cast<const float4*>(tgt  + bb + 512));
        float4 pc0 = __ldcs(reinterpret_cast<const float4*>(pred + bc));
        float4 pc1 = __ldcs(reinterpret_cast<const float4*>(pred + bc + 512));
        float4 tc0 = __ldcs(reinterpret_cast<const float4*>(tgt  + bc));
        float4 tc1 = __ldcs(reinterpret_cast<const float4*>(tgt  + bc + 512));

        acc += block_term(pa0, pa1, ta0, ta1);
        acc += block_term(pb0, pb1, tb0, tb1);
        acc += block_term(pc0, pc1, tc0, tc1);
    }

    // ---- intra-block reduction ----
    #pragma unroll
    for (int off = 16; off > 0; off >>= 1)
        acc += __shfl_down_sync(0xFFFFFFFFu, acc, off);

    __shared__ float warp_sums[NTHREADS / 32];
    int lane = threadIdx.x & 31;
    int wid  = threadIdx.x >> 5;
    if (lane == 0) warp_sums[wid] = acc;
    __syncthreads();

    if (wid == 0) {
        float v = (lane < NTHREADS / 32) ? warp_sums[lane] : 0.0f;
        #pragma unroll
        for (int off = 4; off > 0; off >>= 1)
            v += __shfl_down_sync(0xFFFFFFFFu, v, off);
        if (lane == 0) {
            atomicAdd(&g_sum, (double)v);     // accumulate in double
            __threadfence();                  // publish before ticket
            unsigned t = atomicAdd(&g_count, 1u);
            if (t == NBLOCKS - 1) {
                // last block: all g_sum adds are visible (each preceded its ticket)
                out[0] = (float)(g_sum * INV_COUNT);
                g_sum   = 0.0;                // reset for next graph replay
                g_count = 0;
                __threadfence();
            }
        }
    }
}

extern "C" void kernel_launch(void* const* d_in, const int* in_sizes, int n_in,
                              void* d_out, int out_size) {
    const float* pred = (const float*)d_in[0];
    const float* tgt  = (const float*)d_in[1];
    float* out = (float*)d_out;

    dwt_fused_kernel<<<NBLOCKS, NTHREADS>>>(pred, tgt, out);
}